// round 7
// baseline (speedup 1.0000x reference)
#include <cuda_runtime.h>
#include <cstdint>

#define BB 32
#define CC 256
#define HWL 3136                // 56*56
#define HW4 784                 // HWL/4
#define HID 32
#define NPLANE (BB*CC)          // 8192
#define PLANE_BYTES (HWL * 4)   // 12544
#define NP 8                    // planes per CTA
#define RING 3                  // apply buffer ring depth

__device__ float g_pooled[NPLANE];
__device__ float g_a0[NPLANE];
__device__ float g_c0[NPLANE];
__device__ float g_a1[NPLANE];
__device__ float g_c1[NPLANE];

__device__ __forceinline__ uint32_t smem_u32(const void* p) {
    return (uint32_t)__cvta_generic_to_shared(p);
}

__device__ __forceinline__ void mbar_init(uint32_t mbar, uint32_t cnt) {
    asm volatile("mbarrier.init.shared.b64 [%0], %1;" :: "r"(mbar), "r"(cnt) : "memory");
}
__device__ __forceinline__ void mbar_expect_tx(uint32_t mbar, uint32_t bytes) {
    asm volatile("mbarrier.arrive.expect_tx.shared.b64 _, [%0], %1;"
                 :: "r"(mbar), "r"(bytes) : "memory");
}
__device__ __forceinline__ void mbar_wait(uint32_t mbar, uint32_t parity) {
    asm volatile(
        "{\n\t"
        ".reg .pred P;\n\t"
        "W_%=:\n\t"
        "mbarrier.try_wait.parity.shared.b64 P, [%0], %1;\n\t"
        "@!P bra W_%=;\n\t"
        "}"
        :: "r"(mbar), "r"(parity) : "memory");
}
__device__ __forceinline__ void tma_load_1d(uint32_t dst, const void* src,
                                            uint32_t bytes, uint32_t mbar) {
    asm volatile(
        "cp.async.bulk.shared::cluster.global.mbarrier::complete_tx::bytes "
        "[%0], [%1], %2, [%3];"
        :: "r"(dst), "l"(src), "r"(bytes), "r"(mbar) : "memory");
}
__device__ __forceinline__ void tma_store_1d(void* dst, uint32_t src, uint32_t bytes) {
    asm volatile("cp.async.bulk.global.shared::cta.bulk_group [%0], [%1], %2;"
                 :: "l"(dst), "r"(src), "r"(bytes) : "memory");
}

// ---------------------------------------------------------------------------
// Kernel 1: pooled mean via TMA. 8 planes per CTA, 2-buffer pipeline.
// ---------------------------------------------------------------------------
__global__ __launch_bounds__(256) void pool_tma_kernel(const float* __restrict__ x) {
    __shared__ alignas(16) float buf[2][HWL];
    __shared__ alignas(8) unsigned long long mb[2];
    __shared__ float ws[8];

    const int tid = threadIdx.x;
    const int lane = tid & 31;
    const int warp = tid >> 5;
    const int base = blockIdx.x * NP;
    const uint32_t mba[2] = { smem_u32(&mb[0]), smem_u32(&mb[1]) };
    const uint32_t bufa[2] = { smem_u32(buf[0]), smem_u32(buf[1]) };

    if (tid == 0) { mbar_init(mba[0], 1); mbar_init(mba[1], 1); }
    __syncthreads();
    if (tid == 0) {
        mbar_expect_tx(mba[0], PLANE_BYTES);
        tma_load_1d(bufa[0], x + (size_t)base * HWL, PLANE_BYTES, mba[0]);
    }

    uint32_t ph0 = 0, ph1 = 0;
#pragma unroll
    for (int p = 0; p < NP; p++) {
        const int cur = p & 1;
        // prefetch next plane into the other buffer (read at p-1 is fully done:
        // the reduce below ends with a __syncthreads before anyone reaches here)
        if (tid == 0 && p + 1 < NP) {
            mbar_expect_tx(mba[cur ^ 1], PLANE_BYTES);
            tma_load_1d(bufa[cur ^ 1], x + (size_t)(base + p + 1) * HWL,
                        PLANE_BYTES, mba[cur ^ 1]);
        }
        // wait current plane
        if (cur == 0) { mbar_wait(mba[0], ph0); ph0 ^= 1; }
        else          { mbar_wait(mba[1], ph1); ph1 ^= 1; }

        const float4* t4 = reinterpret_cast<const float4*>(buf[cur]);
        float s = 0.f;
        {
            float4 v0 = t4[tid];
            float4 v1 = t4[tid + 256];
            float4 v2 = t4[tid + 512];
            s = (v0.x + v0.y) + (v0.z + v0.w)
              + (v1.x + v1.y) + (v1.z + v1.w)
              + (v2.x + v2.y) + (v2.z + v2.w);
            if (tid < 16) {
                float4 v3 = t4[768 + tid];
                s += (v3.x + v3.y) + (v3.z + v3.w);
            }
        }
#pragma unroll
        for (int o = 16; o > 0; o >>= 1) s += __shfl_xor_sync(0xffffffffu, s, o);
        if (lane == 0) ws[warp] = s;
        __syncthreads();
        if (tid < 8) {
            s = ws[tid];
#pragma unroll
            for (int o = 4; o > 0; o >>= 1) s += __shfl_xor_sync(0xffu, s, o);
            if (tid == 0) g_pooled[base + p] = s * (1.0f / HWL);
        }
        __syncthreads();   // all reads of buf[cur] done before it is refilled
    }
}

// ---------------------------------------------------------------------------
// Kernel 2: tiny MLP -> per-plane coefficient tables.
// ---------------------------------------------------------------------------
__global__ __launch_bounds__(256) void coef_kernel(const float* __restrict__ fc1_w,
                                                   const float* __restrict__ fc1_b,
                                                   const float* __restrict__ fc2_w,
                                                   const float* __restrict__ fc2_b) {
    const int b = blockIdx.x;
    __shared__ float p_s[CC];
    __shared__ float h_s[HID];

    p_s[threadIdx.x] = g_pooled[b * CC + threadIdx.x];
    __syncthreads();

    {
        const int j = threadIdx.x >> 3;
        const int part = threadIdx.x & 7;
        const float* wrow = fc1_w + j * CC + part * 32;
        const float* pp = p_s + part * 32;
        float acc = 0.f;
#pragma unroll
        for (int i2 = 0; i2 < 32; i2++) acc = fmaf(pp[i2], wrow[i2], acc);
#pragma unroll
        for (int o = 4; o > 0; o >>= 1) acc += __shfl_down_sync(0xffffffffu, acc, o, 8);
        if (part == 0) h_s[j] = fmaxf(acc + fc1_b[j], 0.f);
    }
    __syncthreads();

    const int c = threadIdx.x;
    const float* wa0 = fc2_w + (size_t)(2 * c) * HID;
    const float* wb0 = wa0 + HID;
    const float* wa1 = fc2_w + (size_t)(2 * CC + 2 * c) * HID;
    const float* wb1 = wa1 + HID;
    float da0 = fc2_b[2 * c];
    float db0 = fc2_b[2 * c + 1];
    float da1 = fc2_b[2 * CC + 2 * c];
    float db1 = fc2_b[2 * CC + 2 * c + 1];
#pragma unroll
    for (int j = 0; j < HID; j++) {
        float hj = h_s[j];
        da0 = fmaf(wa0[j], hj, da0);
        db0 = fmaf(wb0[j], hj, db0);
        da1 = fmaf(wa1[j], hj, da1);
        db1 = fmaf(wb1[j], hj, db1);
    }
    const int plane = b * CC + c;
    g_a0[plane] = 1.0f + tanhf(0.5f * da0);          // LAMBDA_ALPHA = 1.0
    g_c0[plane] = 1.0f + 0.5f * tanhf(0.5f * db0);   // LAMBDA_BETA  = 0.5
    g_a1[plane] = tanhf(0.5f * da1);
    g_c1[plane] = 0.5f * tanhf(0.5f * db1);
}

// ---------------------------------------------------------------------------
// Kernel 3: TMA apply, 8 planes per CTA, 3-buffer ring.
// iter p: prefetch p+1 (after wait_group 1 drains the old store of that buf),
//         wait load p, compute in place, syncthreads, bulk-store p + commit.
// ---------------------------------------------------------------------------
__global__ __launch_bounds__(256) void apply_tma_kernel(const float* __restrict__ x,
                                                        float* __restrict__ out) {
    __shared__ alignas(16) float buf[RING][HWL];
    __shared__ alignas(8) unsigned long long mb[RING];

    const int tid = threadIdx.x;
    const int base = blockIdx.x * NP;
    uint32_t mba[RING], bufa[RING];
#pragma unroll
    for (int r = 0; r < RING; r++) { mba[r] = smem_u32(&mb[r]); bufa[r] = smem_u32(buf[r]); }

    if (tid == 0) {
#pragma unroll
        for (int r = 0; r < RING; r++) mbar_init(mba[r], 1);
    }
    __syncthreads();
    if (tid == 0) {
        mbar_expect_tx(mba[0], PLANE_BYTES);
        tma_load_1d(bufa[0], x + (size_t)base * HWL, PLANE_BYTES, mba[0]);
    }

    uint32_t ph[RING] = {0, 0, 0};
#pragma unroll
    for (int p = 0; p < NP; p++) {
        const int cur = p % RING;
        // prefetch plane p+1; its buffer's last store was committed at iter p-2,
        // and at most store p-1 is still outstanding -> wait_group 1.
        if (tid == 0 && p + 1 < NP) {
            const int nxt = (p + 1) % RING;
            asm volatile("cp.async.bulk.wait_group 1;" ::: "memory");
            mbar_expect_tx(mba[nxt], PLANE_BYTES);
            tma_load_1d(bufa[nxt], x + (size_t)(base + p + 1) * HWL,
                        PLANE_BYTES, mba[nxt]);
        }
        mbar_wait(mba[cur], ph[cur]); ph[cur] ^= 1;

        const int plane = base + p;
        const float a0 = g_a0[plane];
        const float c0 = g_c0[plane];
        const float a1 = g_a1[plane];
        const float c1 = g_c1[plane];

        float4* t4 = reinterpret_cast<float4*>(buf[cur]);
        {
            float4 v0 = t4[tid];
            float4 v1 = t4[tid + 256];
            float4 v2 = t4[tid + 512];
            float4 r0, r1, r2;
            r0.x = fmaxf(fmaf(v0.x, a0, c0), fmaf(v0.x, a1, c1));
            r0.y = fmaxf(fmaf(v0.y, a0, c0), fmaf(v0.y, a1, c1));
            r0.z = fmaxf(fmaf(v0.z, a0, c0), fmaf(v0.z, a1, c1));
            r0.w = fmaxf(fmaf(v0.w, a0, c0), fmaf(v0.w, a1, c1));
            r1.x = fmaxf(fmaf(v1.x, a0, c0), fmaf(v1.x, a1, c1));
            r1.y = fmaxf(fmaf(v1.y, a0, c0), fmaf(v1.y, a1, c1));
            r1.z = fmaxf(fmaf(v1.z, a0, c0), fmaf(v1.z, a1, c1));
            r1.w = fmaxf(fmaf(v1.w, a0, c0), fmaf(v1.w, a1, c1));
            r2.x = fmaxf(fmaf(v2.x, a0, c0), fmaf(v2.x, a1, c1));
            r2.y = fmaxf(fmaf(v2.y, a0, c0), fmaf(v2.y, a1, c1));
            r2.z = fmaxf(fmaf(v2.z, a0, c0), fmaf(v2.z, a1, c1));
            r2.w = fmaxf(fmaf(v2.w, a0, c0), fmaf(v2.w, a1, c1));
            t4[tid]       = r0;
            t4[tid + 256] = r1;
            t4[tid + 512] = r2;
            if (tid < 16) {
                float4 v3 = t4[768 + tid];
                float4 r3;
                r3.x = fmaxf(fmaf(v3.x, a0, c0), fmaf(v3.x, a1, c1));
                r3.y = fmaxf(fmaf(v3.y, a0, c0), fmaf(v3.y, a1, c1));
                r3.z = fmaxf(fmaf(v3.z, a0, c0), fmaf(v3.z, a1, c1));
                r3.w = fmaxf(fmaf(v3.w, a0, c0), fmaf(v3.w, a1, c1));
                t4[768 + tid] = r3;
            }
        }
        __syncthreads();
        if (tid == 0) {
            asm volatile("fence.proxy.async.shared::cta;" ::: "memory");
            tma_store_1d(out + (size_t)plane * HWL, bufa[cur], PLANE_BYTES);
            asm volatile("cp.async.bulk.commit_group;" ::: "memory");
        }
    }
    if (tid == 0) asm volatile("cp.async.bulk.wait_group 0;" ::: "memory");
}

extern "C" void kernel_launch(void* const* d_in, const int* in_sizes, int n_in,
                              void* d_out, int out_size) {
    const float* x      = (const float*)d_in[0];
    const float* fc1_w  = (const float*)d_in[1];
    const float* fc1_b  = (const float*)d_in[2];
    const float* fc2_w  = (const float*)d_in[3];
    const float* fc2_b  = (const float*)d_in[4];
    float* out = (float*)d_out;

    pool_tma_kernel<<<NPLANE / NP, 256>>>(x);
    coef_kernel<<<BB, 256>>>(fc1_w, fc1_b, fc2_w, fc2_b);
    apply_tma_kernel<<<NPLANE / NP, 256>>>(x, out);
}

// round 8
// speedup vs baseline: 1.0192x; 1.0192x over previous
#include <cuda_runtime.h>
#include <cstdint>

#define BB 32
#define CC 256
#define HWL 3136                // 56*56
#define HID 32
#define NPLANE (BB*CC)          // 8192
#define PLANE_BYTES (HWL * 4)   // 12544
#define NP 16                   // planes per CTA
#define NCTA (NPLANE / NP)      // 512
#define CTAS_PER_BATCH (CC / NP) // 16
#define RING 3

__device__ float g_pooled[NPLANE];
__device__ unsigned g_bcnt[BB];

__device__ __forceinline__ uint32_t smem_u32(const void* p) {
    return (uint32_t)__cvta_generic_to_shared(p);
}
__device__ __forceinline__ void mbar_init(uint32_t mbar, uint32_t cnt) {
    asm volatile("mbarrier.init.shared.b64 [%0], %1;" :: "r"(mbar), "r"(cnt) : "memory");
}
__device__ __forceinline__ void mbar_expect_tx(uint32_t mbar, uint32_t bytes) {
    asm volatile("mbarrier.arrive.expect_tx.shared.b64 _, [%0], %1;"
                 :: "r"(mbar), "r"(bytes) : "memory");
}
__device__ __forceinline__ void mbar_wait(uint32_t mbar, uint32_t parity) {
    asm volatile(
        "{\n\t"
        ".reg .pred P;\n\t"
        "W_%=:\n\t"
        "mbarrier.try_wait.parity.shared.b64 P, [%0], %1;\n\t"
        "@!P bra W_%=;\n\t"
        "}"
        :: "r"(mbar), "r"(parity) : "memory");
}
__device__ __forceinline__ void tma_load_1d(uint32_t dst, const void* src,
                                            uint32_t bytes, uint32_t mbar) {
    asm volatile(
        "cp.async.bulk.shared::cluster.global.mbarrier::complete_tx::bytes "
        "[%0], [%1], %2, [%3];"
        :: "r"(dst), "l"(src), "r"(bytes), "r"(mbar) : "memory");
}
__device__ __forceinline__ void tma_store_1d(void* dst, uint32_t src, uint32_t bytes) {
    asm volatile("cp.async.bulk.global.shared::cta.bulk_group [%0], [%1], %2;"
                 :: "l"(dst), "r"(src), "r"(bytes) : "memory");
}

// ---------------------------------------------------------------------------
// One persistent kernel: pool own 16 planes -> per-batch sync -> tiny MLP ->
// apply to the same 16 planes (x still hot in L2). Grid = 512 (all resident).
// ---------------------------------------------------------------------------
__global__ __launch_bounds__(256, 4) void fused_kernel(
        const float* __restrict__ x,
        const float* __restrict__ fc1_w,
        const float* __restrict__ fc1_b,
        const float* __restrict__ fc2_w,
        const float* __restrict__ fc2_b,
        float* __restrict__ out) {
    __shared__ alignas(16) float buf[RING][HWL];
    __shared__ alignas(8) unsigned long long mb_pool[2];
    __shared__ alignas(8) unsigned long long mb_ap[RING];
    __shared__ float ws[8];
    __shared__ float p_s[CC];
    __shared__ float h_s[HID];
    __shared__ float sA0[NP], sC0[NP], sA1[NP], sC1[NP];

    const int tid = threadIdx.x;
    const int lane = tid & 31;
    const int warp = tid >> 5;
    const int j = blockIdx.x;
    const int b = j >> 4;                      // batch
    const int cbase = (j & 15) << 4;           // first channel of this CTA
    const int base = j * NP;                   // first plane (= b*CC + cbase)

    uint32_t mpool[2] = { smem_u32(&mb_pool[0]), smem_u32(&mb_pool[1]) };
    uint32_t map[RING], bufa[RING];
#pragma unroll
    for (int r = 0; r < RING; r++) { map[r] = smem_u32(&mb_ap[r]); bufa[r] = smem_u32(buf[r]); }

    if (tid == 0) {
        mbar_init(mpool[0], 1); mbar_init(mpool[1], 1);
#pragma unroll
        for (int r = 0; r < RING; r++) mbar_init(map[r], 1);
    }
    __syncthreads();

    // ---------------- Phase 1: pool 16 planes (2-slot TMA ring) -------------
    if (tid == 0) {
        mbar_expect_tx(mpool[0], PLANE_BYTES);
        tma_load_1d(bufa[0], x + (size_t)base * HWL, PLANE_BYTES, mpool[0]);
    }
    uint32_t php[2] = {0, 0};
#pragma unroll
    for (int p = 0; p < NP; p++) {
        const int cur = p & 1;
        if (tid == 0 && p + 1 < NP) {
            mbar_expect_tx(mpool[cur ^ 1], PLANE_BYTES);
            tma_load_1d(bufa[cur ^ 1], x + (size_t)(base + p + 1) * HWL,
                        PLANE_BYTES, mpool[cur ^ 1]);
        }
        mbar_wait(mpool[cur], php[cur]); php[cur] ^= 1;

        const float4* t4 = reinterpret_cast<const float4*>(buf[cur]);
        float4 v0 = t4[tid];
        float4 v1 = t4[tid + 256];
        float4 v2 = t4[tid + 512];
        float s = (v0.x + v0.y) + (v0.z + v0.w)
                + (v1.x + v1.y) + (v1.z + v1.w)
                + (v2.x + v2.y) + (v2.z + v2.w);
        if (tid < 16) {
            float4 v3 = t4[768 + tid];
            s += (v3.x + v3.y) + (v3.z + v3.w);
        }
#pragma unroll
        for (int o = 16; o > 0; o >>= 1) s += __shfl_xor_sync(0xffffffffu, s, o);
        if (lane == 0) ws[warp] = s;
        __syncthreads();
        if (tid < 8) {
            s = ws[tid];
#pragma unroll
            for (int o = 4; o > 0; o >>= 1) s += __shfl_xor_sync(0xffu, s, o);
            if (tid == 0) g_pooled[base + p] = s * (1.0f / HWL);
        }
        __syncthreads();    // buf[cur] reads done before refill
    }

    // ---------------- Per-batch sync (all 16 CTAs of batch b) ---------------
    if (tid == 0) {
        __threadfence();                     // release g_pooled writes
        atomicAdd(&g_bcnt[b], 1u);
        volatile unsigned* cnt = (volatile unsigned*)&g_bcnt[b];
        while (*cnt < CTAS_PER_BATCH) { }
        __threadfence();                     // acquire
    }
    __syncthreads();

    // ---------------- Phase 2: tiny MLP + coefficients ----------------------
    p_s[tid] = __ldcg(&g_pooled[b * CC + tid]);
    __syncthreads();
    {
        const int jj = tid >> 3;
        const int part = tid & 7;
        const float* wrow = fc1_w + jj * CC + part * 32;
        const float* pp = p_s + part * 32;
        float acc = 0.f;
#pragma unroll
        for (int i2 = 0; i2 < 32; i2++) acc = fmaf(pp[i2], wrow[i2], acc);
#pragma unroll
        for (int o = 4; o > 0; o >>= 1) acc += __shfl_down_sync(0xffffffffu, acc, o, 8);
        if (part == 0) h_s[jj] = fmaxf(acc + fc1_b[jj], 0.f);
    }
    __syncthreads();

    // each warp: 2 channels (lane-redundant dots over HID=32)
#pragma unroll
    for (int t = 0; t < 2; t++) {
        const int lp = warp * 2 + t;             // local plane 0..15
        const int c = cbase + lp;                // global channel
        const float* wa0 = fc2_w + (size_t)(2 * c) * HID;
        const float* wb0 = wa0 + HID;
        const float* wa1 = fc2_w + (size_t)(2 * CC + 2 * c) * HID;
        const float* wb1 = wa1 + HID;
        float da0 = fc2_b[2 * c];
        float db0 = fc2_b[2 * c + 1];
        float da1 = fc2_b[2 * CC + 2 * c];
        float db1 = fc2_b[2 * CC + 2 * c + 1];
#pragma unroll
        for (int q = 0; q < HID; q++) {
            float hq = h_s[q];
            da0 = fmaf(wa0[q], hq, da0);
            db0 = fmaf(wb0[q], hq, db0);
            da1 = fmaf(wa1[q], hq, da1);
            db1 = fmaf(wb1[q], hq, db1);
        }
        if (lane == 0) {
            sA0[lp] = 1.0f + tanhf(0.5f * da0);          // LAMBDA_ALPHA = 1.0
            sC0[lp] = 1.0f + 0.5f * tanhf(0.5f * db0);   // LAMBDA_BETA  = 0.5
            sA1[lp] = tanhf(0.5f * da1);
            sC1[lp] = 0.5f * tanhf(0.5f * db1);
        }
    }
    __syncthreads();

    // ---------------- Phase 3: apply to own 16 planes (3-slot TMA ring) -----
    uint32_t pha[RING] = {0, 0, 0};
    if (tid == 0) {
        mbar_expect_tx(map[0], PLANE_BYTES);
        tma_load_1d(bufa[0], x + (size_t)base * HWL, PLANE_BYTES, map[0]);
    }
#pragma unroll
    for (int p = 0; p < NP; p++) {
        const int cur = p % RING;
        if (tid == 0 && p + 1 < NP) {
            const int nxt = (p + 1) % RING;
            asm volatile("cp.async.bulk.wait_group 1;" ::: "memory"); // drain store p-2
            mbar_expect_tx(map[nxt], PLANE_BYTES);
            tma_load_1d(bufa[nxt], x + (size_t)(base + p + 1) * HWL,
                        PLANE_BYTES, map[nxt]);
        }
        mbar_wait(map[cur], pha[cur]); pha[cur] ^= 1;

        const float a0 = sA0[p], c0 = sC0[p], a1 = sA1[p], c1 = sC1[p];
        float4* t4 = reinterpret_cast<float4*>(buf[cur]);
        float4 v0 = t4[tid];
        float4 v1 = t4[tid + 256];
        float4 v2 = t4[tid + 512];
        float4 r0, r1, r2;
        r0.x = fmaxf(fmaf(v0.x, a0, c0), fmaf(v0.x, a1, c1));
        r0.y = fmaxf(fmaf(v0.y, a0, c0), fmaf(v0.y, a1, c1));
        r0.z = fmaxf(fmaf(v0.z, a0, c0), fmaf(v0.z, a1, c1));
        r0.w = fmaxf(fmaf(v0.w, a0, c0), fmaf(v0.w, a1, c1));
        r1.x = fmaxf(fmaf(v1.x, a0, c0), fmaf(v1.x, a1, c1));
        r1.y = fmaxf(fmaf(v1.y, a0, c0), fmaf(v1.y, a1, c1));
        r1.z = fmaxf(fmaf(v1.z, a0, c0), fmaf(v1.z, a1, c1));
        r1.w = fmaxf(fmaf(v1.w, a0, c0), fmaf(v1.w, a1, c1));
        r2.x = fmaxf(fmaf(v2.x, a0, c0), fmaf(v2.x, a1, c1));
        r2.y = fmaxf(fmaf(v2.y, a0, c0), fmaf(v2.y, a1, c1));
        r2.z = fmaxf(fmaf(v2.z, a0, c0), fmaf(v2.z, a1, c1));
        r2.w = fmaxf(fmaf(v2.w, a0, c0), fmaf(v2.w, a1, c1));
        t4[tid]       = r0;
        t4[tid + 256] = r1;
        t4[tid + 512] = r2;
        if (tid < 16) {
            float4 v3 = t4[768 + tid];
            float4 r3;
            r3.x = fmaxf(fmaf(v3.x, a0, c0), fmaf(v3.x, a1, c1));
            r3.y = fmaxf(fmaf(v3.y, a0, c0), fmaf(v3.y, a1, c1));
            r3.z = fmaxf(fmaf(v3.z, a0, c0), fmaf(v3.z, a1, c1));
            r3.w = fmaxf(fmaf(v3.w, a0, c0), fmaf(v3.w, a1, c1));
            t4[768 + tid] = r3;
        }
        __syncthreads();
        if (tid == 0) {
            asm volatile("fence.proxy.async.shared::cta;" ::: "memory");
            tma_store_1d(out + (size_t)(base + p) * HWL, bufa[cur], PLANE_BYTES);
            asm volatile("cp.async.bulk.commit_group;" ::: "memory");
        }
    }
    if (tid == 0) asm volatile("cp.async.bulk.wait_group 0;" ::: "memory");
}

extern "C" void kernel_launch(void* const* d_in, const int* in_sizes, int n_in,
                              void* d_out, int out_size) {
    const float* x      = (const float*)d_in[0];
    const float* fc1_w  = (const float*)d_in[1];
    const float* fc1_b  = (const float*)d_in[2];
    const float* fc2_w  = (const float*)d_in[3];
    const float* fc2_b  = (const float*)d_in[4];
    float* out = (float*)d_out;

    // reset per-batch counters every call (graph-capturable memset node)
    void* cnt_ptr = nullptr;
    cudaGetSymbolAddress(&cnt_ptr, g_bcnt);
    cudaMemsetAsync(cnt_ptr, 0, BB * sizeof(unsigned), 0);

    fused_kernel<<<NCTA, 256>>>(x, fc1_w, fc1_b, fc2_w, fc2_b, out);
}